// round 7
// baseline (speedup 1.0000x reference)
#include <cuda_runtime.h>
#include <math.h>

#define BB 32
#define NN 2048
#define MM 2048
#define TPB 64
#define BPB (NN / TPB)         // 32 blocks per batch
#define NBLK (BB * BPB)        // 1024 blocks; ~7/SM -> single wave
#define LOG2E 1.4426950408889634f
#define CSHIFT 64.0f           // global log2-domain shift (cancels in softmax ratio)

// Scratch (no allocations allowed)
__device__ float g_T[BB * 4];           // per-batch transform: c, s, tx, ty
__device__ float g_part[NBLK * 8];      // per-block partial sums

__device__ __forceinline__ float ex2(float x) {
    float y;
    asm("ex2.approx.ftz.f32 %0, %1;" : "=f"(y) : "f"(x));
    return y;
}

// ---------------------------------------------------------------------------
// Fused iteration (R4 mainloop — measured at the 5-FFMA/element pipe ceiling)
// + PDL: smem fill and source load run BEFORE the grid dependency sync, so
// they overlap the predecessor update kernel; g_T is read only after sync.
// grid = 1024, block = 64. One source row per thread.
// ---------------------------------------------------------------------------
__global__ __launch_bounds__(TPB, 7)
void iter_kernel(const float* __restrict__ source,
                 const float* __restrict__ target,
                 const float* __restrict__ init,
                 int it) {
    __shared__ float2 smT[MM];     // 16 KB: (tx, ty)
    __shared__ float  smC[MM];     //  8 KB: -log2e*|t|^2 - CSHIFT
    __shared__ float  red[2][8];

    const int tid = threadIdx.x;
    const int b   = blockIdx.x >> 5;
    const int blk = blockIdx.x & 31;

    // ---- pre-sync phase: depends only on target/source ----
    const float4* tg = (const float4*)(target + (size_t)b * MM * 2);
#pragma unroll
    for (int i = 0; i < MM / 2 / TPB; i++) {   // 16 iterations, 2 points each
        int p = tid + i * TPB;
        float4 q = tg[p];                      // tx0, ty0, tx1, ty1
        smT[2 * p + 0] = make_float2(q.x, q.y);
        smT[2 * p + 1] = make_float2(q.z, q.w);
        smC[2 * p + 0] = fmaf(-LOG2E, q.x * q.x + q.y * q.y, -CSHIFT);
        smC[2 * p + 1] = fmaf(-LOG2E, q.z * q.z + q.w * q.w, -CSHIFT);
    }
    const int row = blk * TPB + tid;
    const float2 s2 = ((const float2*)source)[b * NN + row];

    // Allow the dependent kernel (update) to launch early; it parks in its
    // own grid-sync until our g_part writes are complete.
    cudaTriggerProgrammaticLaunchCompletion();

    // Wait for predecessor (update of previous iteration) before reading g_T.
    cudaGridDependencySynchronize();

    float Tc, Ts, Tx, Ty;
    if (it == 0) {
        float th = init[b * 3 + 0];
        Tc = cosf(th); Ts = sinf(th);
        Tx = init[b * 3 + 1]; Ty = init[b * 3 + 2];
    } else {
        Tc = g_T[b * 4 + 0]; Ts = g_T[b * 4 + 1];
        Tx = g_T[b * 4 + 2]; Ty = g_T[b * 4 + 3];
    }

    const float stx = Tc * s2.x - Ts * s2.y + Tx;
    const float sty = Ts * s2.x + Tc * s2.y + Ty;
    const float px  = 2.f * LOG2E * stx;
    const float py  = 2.f * LOG2E * sty;

    __syncthreads();   // smem fill visible to all warps

    // ---- mainloop: 5 fma-pipe ops + 1 MUFU per element ----
    float s0 = 0.f, s1 = 0.f;
    float ax0 = 0.f, ax1 = 0.f;
    float ay0 = 0.f, ay1 = 0.f;

#pragma unroll 8
    for (int m = 0; m < MM; m += 2) {
        float2 t0 = smT[m + 0];
        float2 t1 = smT[m + 1];
        float  c0 = smC[m + 0];
        float  c1 = smC[m + 1];
        float e0 = ex2(fmaf(px, t0.x, fmaf(py, t0.y, c0)));
        float e1 = ex2(fmaf(px, t1.x, fmaf(py, t1.y, c1)));
        s0 += e0; ax0 = fmaf(e0, t0.x, ax0); ay0 = fmaf(e0, t0.y, ay0);
        s1 += e1; ax1 = fmaf(e1, t1.x, ax1); ay1 = fmaf(e1, t1.y, ay1);
    }

    const float inv = 1.0f / (s0 + s1);
    const float tcx = (ax0 + ax1) * inv;
    const float tcy = (ay0 + ay1) * inv;

    // ---- 8-term block reduction ----
    float v[8];
    v[0] = stx;       v[1] = sty;
    v[2] = tcx;       v[3] = tcy;
    v[4] = stx * tcx; v[5] = stx * tcy;
    v[6] = sty * tcx; v[7] = sty * tcy;
#pragma unroll
    for (int off = 16; off > 0; off >>= 1)
#pragma unroll
        for (int k = 0; k < 8; k++)
            v[k] += __shfl_down_sync(0xffffffffu, v[k], off);
    const int wid = tid >> 5, lane = tid & 31;
    if (lane == 0)
#pragma unroll
        for (int k = 0; k < 8; k++) red[wid][k] = v[k];
    __syncthreads();
    if (tid < 8)
        g_part[(b * BPB + blk) * 8 + tid] = red[0][tid] + red[1][tid];
}

// ---------------------------------------------------------------------------
// Update (R4 version): 1 block x 1024 threads. Warp w = batch w. Lane j loads
// block j's 8 partials, fixed-order shuffle tree, lane 0 does fp32 Kabsch
// (polar factor of H^T == V U^T incl. reflection case). PDL: trigger at entry
// so the next iter launches and fills smem while we run.
// ---------------------------------------------------------------------------
__global__ __launch_bounds__(BB * 32)
void update_kernel(const float* __restrict__ init,
                   float* __restrict__ out, int it) {
    cudaTriggerProgrammaticLaunchCompletion();
    cudaGridDependencySynchronize();   // wait for iter's g_part writes

    const int b    = threadIdx.x >> 5;   // batch = warp id
    const int lane = threadIdx.x & 31;   // block index within batch (BPB == 32)

    const float4* p = (const float4*)&g_part[(b * BPB + lane) * 8];
    float4 qa = p[0];
    float4 qb = p[1];
    float v[8] = {qa.x, qa.y, qa.z, qa.w, qb.x, qb.y, qb.z, qb.w};

#pragma unroll
    for (int off = 16; off > 0; off >>= 1)
#pragma unroll
        for (int k = 0; k < 8; k++)
            v[k] += __shfl_down_sync(0xffffffffu, v[k], off);

    if (lane != 0) return;

    const float inN = 1.0f / (float)NN;
    const float csx = v[0] * inN, csy = v[1] * inN;
    const float ctx = v[2] * inN, cty = v[3] * inN;
    const float H00 = v[4] - v[0] * v[2] * inN;
    const float H01 = v[5] - v[0] * v[3] * inN;
    const float H10 = v[6] - v[1] * v[2] * inN;
    const float H11 = v[7] - v[1] * v[3] * inN;

    // Polar factor of A = H^T: rotation part vs reflection part.
    const float b0 = H00 + H11, b1 = H10 - H01;
    const float c0 = H00 - H11, c1 = H10 + H01;
    const float nb  = b0 * b0 + b1 * b1;
    const float nc2 = c0 * c0 + c1 * c1;

    float R00, R01, R10, R11;
    if (nb >= nc2) {
        float ih = (nb > 0.f) ? rsqrtf(nb) : 0.f;
        R00 = b0 * ih;  R01 = b1 * ih;
        R10 = -b1 * ih; R11 = b0 * ih;
    } else {
        float ih = (nc2 > 0.f) ? rsqrtf(nc2) : 0.f;
        R00 = c0 * ih;  R01 = c1 * ih;
        R10 = c1 * ih;  R11 = -c0 * ih;
    }
    const float tdx = ctx - (R00 * csx + R01 * csy);
    const float tdy = cty - (R10 * csx + R11 * csy);

    // Applied delta rotation = normalize(R00, R10) (matches vec2mat(atan2)).
    const float nn2 = R00 * R00 + R10 * R10;
    const float inh = (nn2 > 0.f) ? rsqrtf(nn2) : 0.f;
    const float cd = R00 * inh, sd = R10 * inh;

    float oc, os, ox, oy;
    if (it == 0) {
        float th = init[b * 3 + 0];
        oc = cosf(th); os = sinf(th);
        ox = init[b * 3 + 1]; oy = init[b * 3 + 2];
    } else {
        oc = g_T[b * 4 + 0]; os = g_T[b * 4 + 1];
        ox = g_T[b * 4 + 2]; oy = g_T[b * 4 + 3];
    }

    const float nc  = cd * oc - sd * os;
    const float ns  = sd * oc + cd * os;
    const float ntx = cd * ox - sd * oy + tdx;
    const float nty = sd * ox + cd * oy + tdy;

    g_T[b * 4 + 0] = nc;  g_T[b * 4 + 1] = ns;
    g_T[b * 4 + 2] = ntx; g_T[b * 4 + 3] = nty;

    if (it == 4) {
        out[b * 3 + 0] = atan2f(ns, nc);
        out[b * 3 + 1] = ntx;
        out[b * 3 + 2] = nty;
    }
}

// ---------------------------------------------------------------------------
extern "C" void kernel_launch(void* const* d_in, const int* in_sizes, int n_in,
                              void* d_out, int out_size) {
    const float* source = (const float*)d_in[0];
    const float* target = (const float*)d_in[1];
    const float* init   = (const float*)d_in[2];
    float* out = (float*)d_out;

    cudaLaunchAttribute attr[1];
    attr[0].id = cudaLaunchAttributeProgrammaticStreamSerialization;
    attr[0].val.programmaticStreamSerializationAllowed = 1;

    for (int it = 0; it < 5; it++) {
        // iter
        {
            cudaLaunchConfig_t cfg = {};
            cfg.gridDim  = dim3(NBLK, 1, 1);
            cfg.blockDim = dim3(TPB, 1, 1);
            cfg.dynamicSmemBytes = 0;
            cfg.stream = 0;
            cfg.attrs = attr;
            cfg.numAttrs = (it == 0) ? 0 : 1;   // first node: no PDL edge
            cudaLaunchKernelEx(&cfg, iter_kernel, source, target, init, it);
        }
        // update
        {
            cudaLaunchConfig_t cfg = {};
            cfg.gridDim  = dim3(1, 1, 1);
            cfg.blockDim = dim3(BB * 32, 1, 1);
            cfg.dynamicSmemBytes = 0;
            cfg.stream = 0;
            cfg.attrs = attr;
            cfg.numAttrs = 1;
            cudaLaunchKernelEx(&cfg, update_kernel, init, out, it);
        }
    }
}

// round 9
// speedup vs baseline: 1.2005x; 1.2005x over previous
#include <cuda_runtime.h>
#include <math.h>

#define BB 32
#define NN 2048
#define MM 2048
#define TPB 64
#define BPB (NN / TPB)         // 32 blocks per batch
#define NBLK (BB * BPB)        // 1024 blocks; ~7/SM -> single wave
#define LOG2E 1.4426950408889634f
#define CSHIFT 64.0f           // global log2-domain shift (cancels in softmax ratio)

// Scratch (no allocations allowed)
__device__ float    g_T[BB * 4];        // per-batch transform: c, s, tx, ty
__device__ float    g_part[NBLK * 8];   // per-block partial sums
__device__ unsigned g_ctr[BB];          // monotonic per-batch arrival counters

__device__ __forceinline__ float ex2(float x) {
    float y;
    asm("ex2.approx.ftz.f32 %0, %1;" : "=f"(y) : "f"(x));
    return y;
}

// ---------------------------------------------------------------------------
// Single kernel type, 5 launches. Prologue + mainloop are byte-identical to
// the proven R4 iter (38.6us, ~97% of the 5-FFMA/element pipe ceiling).
// Epilogue: the last-arriving block of each batch folds in the Kabsch update
// (reads the batch's 32 partials via L2, composes T, writes g_T; on it==4
// writes the output). Stream-order launch boundaries provide the cross-
// iteration sync, so no update kernel and no spinning are needed.
// ---------------------------------------------------------------------------
__global__ __launch_bounds__(TPB, 7)
void iter_kernel(const float* __restrict__ source,
                 const float* __restrict__ target,
                 const float* __restrict__ init,
                 float* __restrict__ out,
                 int it) {
    __shared__ float2 smT[MM];     // 16 KB: (tx, ty)
    __shared__ float  smC[MM];     //  8 KB: -log2e*|t|^2 - CSHIFT
    __shared__ float  red[2][8];
    __shared__ unsigned s_win;

    const int tid = threadIdx.x;
    const int b   = blockIdx.x >> 5;
    const int blk = blockIdx.x & 31;

    // ---- smem fill: raw target -> coefficients ----
    const float4* tg = (const float4*)(target + (size_t)b * MM * 2);
#pragma unroll
    for (int i = 0; i < MM / 2 / TPB; i++) {   // 16 iterations, 2 points each
        int p = tid + i * TPB;
        float4 q = tg[p];                      // tx0, ty0, tx1, ty1
        smT[2 * p + 0] = make_float2(q.x, q.y);
        smT[2 * p + 1] = make_float2(q.z, q.w);
        smC[2 * p + 0] = fmaf(-LOG2E, q.x * q.x + q.y * q.y, -CSHIFT);
        smC[2 * p + 1] = fmaf(-LOG2E, q.z * q.z + q.w * q.w, -CSHIFT);
    }

    // ---- transform for this iteration (T_it) ----
    float Tc, Ts, Tx, Ty;
    if (it == 0) {
        float th = init[b * 3 + 0];
        Tc = cosf(th); Ts = sinf(th);
        Tx = init[b * 3 + 1]; Ty = init[b * 3 + 2];
    } else {
        Tc = g_T[b * 4 + 0]; Ts = g_T[b * 4 + 1];
        Tx = g_T[b * 4 + 2]; Ty = g_T[b * 4 + 3];
    }

    const int row = blk * TPB + tid;
    const float2 s2 = ((const float2*)source)[b * NN + row];
    const float stx = Tc * s2.x - Ts * s2.y + Tx;
    const float sty = Ts * s2.x + Tc * s2.y + Ty;
    const float px  = 2.f * LOG2E * stx;
    const float py  = 2.f * LOG2E * sty;

    __syncthreads();

    // ---- mainloop: 5 fma-pipe ops + 1 MUFU per element (at pipe ceiling) ----
    float s0 = 0.f, s1 = 0.f;
    float ax0 = 0.f, ax1 = 0.f;
    float ay0 = 0.f, ay1 = 0.f;

#pragma unroll 8
    for (int m = 0; m < MM; m += 2) {
        float2 t0 = smT[m + 0];
        float2 t1 = smT[m + 1];
        float  c0 = smC[m + 0];
        float  c1 = smC[m + 1];
        float e0 = ex2(fmaf(px, t0.x, fmaf(py, t0.y, c0)));
        float e1 = ex2(fmaf(px, t1.x, fmaf(py, t1.y, c1)));
        s0 += e0; ax0 = fmaf(e0, t0.x, ax0); ay0 = fmaf(e0, t0.y, ay0);
        s1 += e1; ax1 = fmaf(e1, t1.x, ax1); ay1 = fmaf(e1, t1.y, ay1);
    }

    const float inv = 1.0f / (s0 + s1);
    const float tcx = (ax0 + ax1) * inv;
    const float tcy = (ay0 + ay1) * inv;

    // ---- 8-term block reduction ----
    float v[8];
    v[0] = stx;       v[1] = sty;
    v[2] = tcx;       v[3] = tcy;
    v[4] = stx * tcx; v[5] = stx * tcy;
    v[6] = sty * tcx; v[7] = sty * tcy;
#pragma unroll
    for (int off = 16; off > 0; off >>= 1)
#pragma unroll
        for (int k = 0; k < 8; k++)
            v[k] += __shfl_down_sync(0xffffffffu, v[k], off);
    const int wid = tid >> 5, lane = tid & 31;
    if (lane == 0)
#pragma unroll
        for (int k = 0; k < 8; k++) red[wid][k] = v[k];
    __syncthreads();
    if (tid < 8)
        g_part[(b * BPB + blk) * 8 + tid] = red[0][tid] + red[1][tid];

    // ---- release partials, elect the per-batch updater (last arrival) ----
    __threadfence();
    __syncthreads();
    if (tid == 0) {
        unsigned a = atomicAdd(&g_ctr[b], 1u) + 1u;   // monotonic across replays
        s_win = ((a & 31u) == 0u) ? 1u : 0u;
    }
    __syncthreads();

    // ---- folded update: winner block's warp 0 composes T_{it+1} ----
    if (s_win && tid < 32) {
        __threadfence();   // acquire: order counter observation before reads
        const float4* pp = (const float4*)&g_part[(b * BPB + tid) * 8];
        float4 qa = __ldcg(pp);         // .cg: bypass possibly-stale L1 line
        float4 qb = __ldcg(pp + 1);
        float w[8] = {qa.x, qa.y, qa.z, qa.w, qb.x, qb.y, qb.z, qb.w};
#pragma unroll
        for (int off = 16; off > 0; off >>= 1)
#pragma unroll
            for (int k = 0; k < 8; k++)
                w[k] += __shfl_down_sync(0xffffffffu, w[k], off);

        if (tid == 0) {
            const float inN = 1.0f / (float)NN;
            const float csx = w[0] * inN, csy = w[1] * inN;
            const float ctx = w[2] * inN, cty = w[3] * inN;
            const float H00 = w[4] - w[0] * w[2] * inN;
            const float H01 = w[5] - w[0] * w[3] * inN;
            const float H10 = w[6] - w[1] * w[2] * inN;
            const float H11 = w[7] - w[1] * w[3] * inN;

            // Polar factor of H^T == V U^T of the SVD incl. reflection case.
            const float b0 = H00 + H11, b1 = H10 - H01;
            const float c0 = H00 - H11, c1 = H10 + H01;
            const float nb  = b0 * b0 + b1 * b1;
            const float nc2 = c0 * c0 + c1 * c1;

            float R00, R01, R10, R11;
            if (nb >= nc2) {
                float ih = (nb > 0.f) ? rsqrtf(nb) : 0.f;
                R00 = b0 * ih;  R01 = b1 * ih;
                R10 = -b1 * ih; R11 = b0 * ih;
            } else {
                float ih = (nc2 > 0.f) ? rsqrtf(nc2) : 0.f;
                R00 = c0 * ih;  R01 = c1 * ih;
                R10 = c1 * ih;  R11 = -c0 * ih;
            }
            const float tdx = ctx - (R00 * csx + R01 * csy);
            const float tdy = cty - (R10 * csx + R11 * csy);

            // Applied delta rotation = normalize(R00, R10) (== vec2mat(atan2)).
            const float nn2 = R00 * R00 + R10 * R10;
            const float inh = (nn2 > 0.f) ? rsqrtf(nn2) : 0.f;
            const float cd = R00 * inh, sd = R10 * inh;

            const float nc  = cd * Tc - sd * Ts;     // old T_it still live
            const float ns  = sd * Tc + cd * Ts;
            const float ntx = cd * Tx - sd * Ty + tdx;
            const float nty = sd * Tx + cd * Ty + tdy;

            g_T[b * 4 + 0] = nc;  g_T[b * 4 + 1] = ns;
            g_T[b * 4 + 2] = ntx; g_T[b * 4 + 3] = nty;

            if (it == 4) {
                out[b * 3 + 0] = atan2f(ns, nc);
                out[b * 3 + 1] = ntx;
                out[b * 3 + 2] = nty;
            }
        }
    }
}

// ---------------------------------------------------------------------------
extern "C" void kernel_launch(void* const* d_in, const int* in_sizes, int n_in,
                              void* d_out, int out_size) {
    const float* source = (const float*)d_in[0];
    const float* target = (const float*)d_in[1];
    const float* init   = (const float*)d_in[2];
    float* out = (float*)d_out;

    for (int it = 0; it < 5; it++)
        iter_kernel<<<NBLK, TPB>>>(source, target, init, out, it);
}

// round 10
// speedup vs baseline: 1.2290x; 1.0238x over previous
#include <cuda_runtime.h>
#include <math.h>

#define BB 32
#define NN 2048
#define MM 2048
#define TPB 32                  // 1 warp per block
#define ROWS_PER_BLK 64         // 2 rows per thread
#define BPB (NN / ROWS_PER_BLK) // 32 blocks per batch (unchanged vs R8)
#define NBLK (BB * BPB)         // 1024 blocks; ~7/SM -> single wave, 1.2% imbalance
#define LOG2E 1.4426950408889634f
#define CSHIFT 64.0f            // global log2-domain shift (cancels in softmax ratio)

// Scratch (no allocations allowed)
__device__ float    g_T[BB * 4];        // per-batch transform: c, s, tx, ty
__device__ float    g_part[NBLK * 8];   // per-block partial sums
__device__ unsigned g_ctr[BB];          // monotonic per-batch arrival counters

__device__ __forceinline__ float ex2(float x) {
    float y;
    asm("ex2.approx.ftz.f32 %0, %1;" : "=f"(y) : "f"(x));
    return y;
}

// ---------------------------------------------------------------------------
// Single kernel type, 5 launches (stream order = cross-iteration sync).
// 2 source rows per thread: each smem target element feeds both rows, halving
// LDS traffic and loop overhead per element. Mainloop stays 5 FFMA + 1 MUFU
// per element. Epilogue: last-arriving block of each batch does the Kabsch
// update (proven R8 pattern).
// ---------------------------------------------------------------------------
__global__ __launch_bounds__(TPB, 7)
void iter_kernel(const float* __restrict__ source,
                 const float* __restrict__ target,
                 const float* __restrict__ init,
                 float* __restrict__ out,
                 int it) {
    __shared__ float2 smT[MM];     // 16 KB: (tx, ty)
    __shared__ float  smC[MM];     //  8 KB: -log2e*|t|^2 - CSHIFT
    __shared__ unsigned s_win;

    const int tid = threadIdx.x;           // lane (1 warp)
    const int b   = blockIdx.x >> 5;
    const int blk = blockIdx.x & 31;

    // ---- smem fill: raw target -> coefficients ----
    const float4* tg = (const float4*)(target + (size_t)b * MM * 2);
#pragma unroll
    for (int i = 0; i < MM / 2 / TPB; i++) {   // 32 iterations, 2 points each
        int p = tid + i * TPB;
        float4 q = tg[p];                      // tx0, ty0, tx1, ty1
        smT[2 * p + 0] = make_float2(q.x, q.y);
        smT[2 * p + 1] = make_float2(q.z, q.w);
        smC[2 * p + 0] = fmaf(-LOG2E, q.x * q.x + q.y * q.y, -CSHIFT);
        smC[2 * p + 1] = fmaf(-LOG2E, q.z * q.z + q.w * q.w, -CSHIFT);
    }

    // ---- transform for this iteration (T_it) ----
    float Tc, Ts, Tx, Ty;
    if (it == 0) {
        float th = init[b * 3 + 0];
        Tc = cosf(th); Ts = sinf(th);
        Tx = init[b * 3 + 1]; Ty = init[b * 3 + 2];
    } else {
        Tc = g_T[b * 4 + 0]; Ts = g_T[b * 4 + 1];
        Tx = g_T[b * 4 + 2]; Ty = g_T[b * 4 + 3];
    }

    // Two rows per thread: rA = blk*64 + lane, rB = rA + 32 (both coalesced).
    const int rA = blk * ROWS_PER_BLK + tid;
    const int rB = rA + 32;
    const float2 sA = ((const float2*)source)[b * NN + rA];
    const float2 sB = ((const float2*)source)[b * NN + rB];

    const float stxA = Tc * sA.x - Ts * sA.y + Tx;
    const float styA = Ts * sA.x + Tc * sA.y + Ty;
    const float stxB = Tc * sB.x - Ts * sB.y + Tx;
    const float styB = Ts * sB.x + Tc * sB.y + Ty;
    const float pxA  = 2.f * LOG2E * stxA;
    const float pyA  = 2.f * LOG2E * styA;
    const float pxB  = 2.f * LOG2E * stxB;
    const float pyB  = 2.f * LOG2E * styB;

    __syncthreads();

    // ---- mainloop: per target element, 2 rows: 10 fma-pipe + 2 MUFU,
    //      amortized LDS = 1.5 per 2 elements ----
    float sA0 = 0.f, sA1 = 0.f, axA0 = 0.f, axA1 = 0.f, ayA0 = 0.f, ayA1 = 0.f;
    float sB0 = 0.f, sB1 = 0.f, axB0 = 0.f, axB1 = 0.f, ayB0 = 0.f, ayB1 = 0.f;

#pragma unroll 4
    for (int m = 0; m < MM; m += 2) {
        float2 t0 = smT[m + 0];
        float2 t1 = smT[m + 1];
        float  c0 = smC[m + 0];
        float  c1 = smC[m + 1];
        float eA0 = ex2(fmaf(pxA, t0.x, fmaf(pyA, t0.y, c0)));
        float eA1 = ex2(fmaf(pxA, t1.x, fmaf(pyA, t1.y, c1)));
        float eB0 = ex2(fmaf(pxB, t0.x, fmaf(pyB, t0.y, c0)));
        float eB1 = ex2(fmaf(pxB, t1.x, fmaf(pyB, t1.y, c1)));
        sA0 += eA0; axA0 = fmaf(eA0, t0.x, axA0); ayA0 = fmaf(eA0, t0.y, ayA0);
        sA1 += eA1; axA1 = fmaf(eA1, t1.x, axA1); ayA1 = fmaf(eA1, t1.y, ayA1);
        sB0 += eB0; axB0 = fmaf(eB0, t0.x, axB0); ayB0 = fmaf(eB0, t0.y, ayB0);
        sB1 += eB1; axB1 = fmaf(eB1, t1.x, axB1); ayB1 = fmaf(eB1, t1.y, ayB1);
    }

    const float invA = 1.0f / (sA0 + sA1);
    const float tcxA = (axA0 + axA1) * invA;
    const float tcyA = (ayA0 + ayA1) * invA;
    const float invB = 1.0f / (sB0 + sB1);
    const float tcxB = (axB0 + axB1) * invB;
    const float tcyB = (ayB0 + ayB1) * invB;

    // ---- 8-term reduction (both rows summed per thread, then warp tree) ----
    float v[8];
    v[0] = stxA + stxB;
    v[1] = styA + styB;
    v[2] = tcxA + tcxB;
    v[3] = tcyA + tcyB;
    v[4] = stxA * tcxA + stxB * tcxB;
    v[5] = stxA * tcyA + stxB * tcyB;
    v[6] = styA * tcxA + styB * tcxB;
    v[7] = styA * tcyA + styB * tcyB;
#pragma unroll
    for (int off = 16; off > 0; off >>= 1)
#pragma unroll
        for (int k = 0; k < 8; k++)
            v[k] += __shfl_down_sync(0xffffffffu, v[k], off);

    if (tid < 8) {
        // broadcast v[k] (held by lane 0) to lane k, then coalesced store
        float r = 0.f;
#pragma unroll
        for (int k = 0; k < 8; k++) {
            float t = __shfl_sync(0x000000ffu, v[k], 0, 8);
            if (tid == k) r = t;
        }
        g_part[(b * BPB + blk) * 8 + tid] = r;
    }

    // ---- release partials, elect the per-batch updater (last arrival) ----
    __threadfence();
    __syncthreads();
    if (tid == 0) {
        unsigned a = atomicAdd(&g_ctr[b], 1u) + 1u;   // monotonic across replays
        s_win = ((a & 31u) == 0u) ? 1u : 0u;
    }
    __syncthreads();

    // ---- folded update: winner block composes T_{it+1} ----
    if (s_win) {
        __threadfence();   // acquire: order counter observation before reads
        const float4* pp = (const float4*)&g_part[(b * BPB + tid) * 8];
        float4 qa = __ldcg(pp);         // .cg: bypass possibly-stale L1 line
        float4 qb = __ldcg(pp + 1);
        float w[8] = {qa.x, qa.y, qa.z, qa.w, qb.x, qb.y, qb.z, qb.w};
#pragma unroll
        for (int off = 16; off > 0; off >>= 1)
#pragma unroll
            for (int k = 0; k < 8; k++)
                w[k] += __shfl_down_sync(0xffffffffu, w[k], off);

        if (tid == 0) {
            const float inN = 1.0f / (float)NN;
            const float csx = w[0] * inN, csy = w[1] * inN;
            const float ctx = w[2] * inN, cty = w[3] * inN;
            const float H00 = w[4] - w[0] * w[2] * inN;
            const float H01 = w[5] - w[0] * w[3] * inN;
            const float H10 = w[6] - w[1] * w[2] * inN;
            const float H11 = w[7] - w[1] * w[3] * inN;

            // Polar factor of H^T == V U^T of the SVD incl. reflection case.
            const float b0 = H00 + H11, b1 = H10 - H01;
            const float c0 = H00 - H11, c1 = H10 + H01;
            const float nb  = b0 * b0 + b1 * b1;
            const float nc2 = c0 * c0 + c1 * c1;

            float R00, R01, R10, R11;
            if (nb >= nc2) {
                float ih = (nb > 0.f) ? rsqrtf(nb) : 0.f;
                R00 = b0 * ih;  R01 = b1 * ih;
                R10 = -b1 * ih; R11 = b0 * ih;
            } else {
                float ih = (nc2 > 0.f) ? rsqrtf(nc2) : 0.f;
                R00 = c0 * ih;  R01 = c1 * ih;
                R10 = c1 * ih;  R11 = -c0 * ih;
            }
            const float tdx = ctx - (R00 * csx + R01 * csy);
            const float tdy = cty - (R10 * csx + R11 * csy);

            // Applied delta rotation = normalize(R00, R10) (== vec2mat(atan2)).
            const float nn2 = R00 * R00 + R10 * R10;
            const float inh = (nn2 > 0.f) ? rsqrtf(nn2) : 0.f;
            const float cd = R00 * inh, sd = R10 * inh;

            const float nc  = cd * Tc - sd * Ts;     // old T_it still live
            const float ns  = sd * Tc + cd * Ts;
            const float ntx = cd * Tx - sd * Ty + tdx;
            const float nty = sd * Tx + cd * Ty + tdy;

            g_T[b * 4 + 0] = nc;  g_T[b * 4 + 1] = ns;
            g_T[b * 4 + 2] = ntx; g_T[b * 4 + 3] = nty;

            if (it == 4) {
                out[b * 3 + 0] = atan2f(ns, nc);
                out[b * 3 + 1] = ntx;
                out[b * 3 + 2] = nty;
            }
        }
    }
}

// ---------------------------------------------------------------------------
extern "C" void kernel_launch(void* const* d_in, const int* in_sizes, int n_in,
                              void* d_out, int out_size) {
    const float* source = (const float*)d_in[0];
    const float* target = (const float*)d_in[1];
    const float* init   = (const float*)d_in[2];
    float* out = (float*)d_out;

    for (int it = 0; it < 5; it++)
        iter_kernel<<<NBLK, TPB>>>(source, target, init, out, it);
}

// round 11
// speedup vs baseline: 1.2447x; 1.0128x over previous
#include <cuda_runtime.h>
#include <math.h>

#define BB 32
#define NN 2048
#define MM 2048
#define TPB 32                  // 1 warp per block
#define ROWS_PER_BLK 64         // 2 rows per thread
#define BPB (NN / ROWS_PER_BLK) // 32 blocks per batch
#define NBLK (BB * BPB)         // 1024 blocks; ~7/SM -> single wave
#define LOG2E 1.4426950408889634f
#define CSHIFT 64.0f            // global log2-domain shift (cancels in softmax ratio)

// Scratch (no allocations allowed)
__device__ float    g_T[BB * 4];        // per-batch transform: c, s, tx, ty
__device__ float    g_part[NBLK * 8];   // per-block partial sums
__device__ unsigned g_ctr[BB];          // monotonic per-batch arrival counters

__device__ __forceinline__ float ex2(float x) {
    float y;
    asm("ex2.approx.ftz.f32 %0, %1;" : "=f"(y) : "f"(x));
    return y;
}

// ---------------------------------------------------------------------------
// Single kernel type, 5 launches (stream order = cross-iteration sync).
// smT keeps the GLOBAL float4 layout (tx0,ty0,tx1,ty1) -> prologue is a raw
// copy and the mainloop reads one LDS.128 + one LDS.64 per 2 targets.
// 2 source rows per thread amortize LDS/loop overhead. Epilogue: last-arriving
// block per batch does the Kabsch update (proven R8 pattern).
// ---------------------------------------------------------------------------
__global__ __launch_bounds__(TPB, 7)
void iter_kernel(const float* __restrict__ source,
                 const float* __restrict__ target,
                 const float* __restrict__ init,
                 float* __restrict__ out,
                 int it) {
    __shared__ float4 smT[MM / 2];   // 16 KB: (tx0, ty0, tx1, ty1) — raw copy
    __shared__ float2 smC[MM / 2];   //  8 KB: (c0, c1), c = -log2e*|t|^2 - CSHIFT
    __shared__ unsigned s_win;

    const int tid = threadIdx.x;           // lane (1 warp)
    const int b   = blockIdx.x >> 5;
    const int blk = blockIdx.x & 31;

    // ---- smem fill: verbatim tile copy + per-pair c coefficients ----
    const float4* tg = (const float4*)(target + (size_t)b * MM * 2);
#pragma unroll
    for (int i = 0; i < MM / 2 / TPB; i++) {   // 32 iterations, 2 points each
        int p = tid + i * TPB;
        float4 q = tg[p];                      // tx0, ty0, tx1, ty1
        smT[p] = q;
        smC[p] = make_float2(fmaf(-LOG2E, q.x * q.x + q.y * q.y, -CSHIFT),
                             fmaf(-LOG2E, q.z * q.z + q.w * q.w, -CSHIFT));
    }

    // ---- transform for this iteration (T_it) ----
    float Tc, Ts, Tx, Ty;
    if (it == 0) {
        float th = init[b * 3 + 0];
        Tc = cosf(th); Ts = sinf(th);
        Tx = init[b * 3 + 1]; Ty = init[b * 3 + 2];
    } else {
        Tc = g_T[b * 4 + 0]; Ts = g_T[b * 4 + 1];
        Tx = g_T[b * 4 + 2]; Ty = g_T[b * 4 + 3];
    }

    // Two rows per thread: rA = blk*64 + lane, rB = rA + 32 (both coalesced).
    const int rA = blk * ROWS_PER_BLK + tid;
    const int rB = rA + 32;
    const float2 sA = ((const float2*)source)[b * NN + rA];
    const float2 sB = ((const float2*)source)[b * NN + rB];

    const float stxA = Tc * sA.x - Ts * sA.y + Tx;
    const float styA = Ts * sA.x + Tc * sA.y + Ty;
    const float stxB = Tc * sB.x - Ts * sB.y + Tx;
    const float styB = Ts * sB.x + Tc * sB.y + Ty;
    const float pxA  = 2.f * LOG2E * stxA;
    const float pyA  = 2.f * LOG2E * styA;
    const float pxB  = 2.f * LOG2E * stxB;
    const float pyB  = 2.f * LOG2E * styB;

    __syncthreads();

    // ---- mainloop: per 2 targets x 2 rows: 20 FFMA + 4 MUFU + 2 LDS ----
    float sA0 = 0.f, sA1 = 0.f, axA0 = 0.f, axA1 = 0.f, ayA0 = 0.f, ayA1 = 0.f;
    float sB0 = 0.f, sB1 = 0.f, axB0 = 0.f, axB1 = 0.f, ayB0 = 0.f, ayB1 = 0.f;

#pragma unroll 8
    for (int p = 0; p < MM / 2; p++) {
        float4 t = smT[p];          // one LDS.128 (broadcast, conflict-free)
        float2 c = smC[p];          // one LDS.64
        float eA0 = ex2(fmaf(pxA, t.x, fmaf(pyA, t.y, c.x)));
        float eA1 = ex2(fmaf(pxA, t.z, fmaf(pyA, t.w, c.y)));
        float eB0 = ex2(fmaf(pxB, t.x, fmaf(pyB, t.y, c.x)));
        float eB1 = ex2(fmaf(pxB, t.z, fmaf(pyB, t.w, c.y)));
        sA0 += eA0; axA0 = fmaf(eA0, t.x, axA0); ayA0 = fmaf(eA0, t.y, ayA0);
        sA1 += eA1; axA1 = fmaf(eA1, t.z, axA1); ayA1 = fmaf(eA1, t.w, ayA1);
        sB0 += eB0; axB0 = fmaf(eB0, t.x, axB0); ayB0 = fmaf(eB0, t.y, ayB0);
        sB1 += eB1; axB1 = fmaf(eB1, t.z, axB1); ayB1 = fmaf(eB1, t.w, ayB1);
    }

    const float invA = 1.0f / (sA0 + sA1);
    const float tcxA = (axA0 + axA1) * invA;
    const float tcyA = (ayA0 + ayA1) * invA;
    const float invB = 1.0f / (sB0 + sB1);
    const float tcxB = (axB0 + axB1) * invB;
    const float tcyB = (ayB0 + ayB1) * invB;

    // ---- 8-term reduction (both rows summed per thread, then warp tree) ----
    float v[8];
    v[0] = stxA + stxB;
    v[1] = styA + styB;
    v[2] = tcxA + tcxB;
    v[3] = tcyA + tcyB;
    v[4] = stxA * tcxA + stxB * tcxB;
    v[5] = stxA * tcyA + stxB * tcyB;
    v[6] = styA * tcxA + styB * tcxB;
    v[7] = styA * tcyA + styB * tcyB;
#pragma unroll
    for (int off = 16; off > 0; off >>= 1)
#pragma unroll
        for (int k = 0; k < 8; k++)
            v[k] += __shfl_down_sync(0xffffffffu, v[k], off);

    if (tid == 0) {
#pragma unroll
        for (int k = 0; k < 8; k++)
            g_part[(b * BPB + blk) * 8 + k] = v[k];
    }

    // ---- release partials, elect the per-batch updater (last arrival) ----
    __threadfence();
    __syncthreads();
    if (tid == 0) {
        unsigned a = atomicAdd(&g_ctr[b], 1u) + 1u;   // monotonic across replays
        s_win = ((a & 31u) == 0u) ? 1u : 0u;
    }
    __syncthreads();

    // ---- folded update: winner block composes T_{it+1} ----
    if (s_win) {
        __threadfence();   // acquire: order counter observation before reads
        const float4* pp = (const float4*)&g_part[(b * BPB + tid) * 8];
        float4 qa = __ldcg(pp);         // .cg: bypass possibly-stale L1 line
        float4 qb = __ldcg(pp + 1);
        float w[8] = {qa.x, qa.y, qa.z, qa.w, qb.x, qb.y, qb.z, qb.w};
#pragma unroll
        for (int off = 16; off > 0; off >>= 1)
#pragma unroll
            for (int k = 0; k < 8; k++)
                w[k] += __shfl_down_sync(0xffffffffu, w[k], off);

        if (tid == 0) {
            const float inN = 1.0f / (float)NN;
            const float csx = w[0] * inN, csy = w[1] * inN;
            const float ctx = w[2] * inN, cty = w[3] * inN;
            const float H00 = w[4] - w[0] * w[2] * inN;
            const float H01 = w[5] - w[0] * w[3] * inN;
            const float H10 = w[6] - w[1] * w[2] * inN;
            const float H11 = w[7] - w[1] * w[3] * inN;

            // Polar factor of H^T == V U^T of the SVD incl. reflection case.
            const float b0 = H00 + H11, b1 = H10 - H01;
            const float c0 = H00 - H11, c1 = H10 + H01;
            const float nb  = b0 * b0 + b1 * b1;
            const float nc2 = c0 * c0 + c1 * c1;

            float R00, R01, R10, R11;
            if (nb >= nc2) {
                float ih = (nb > 0.f) ? rsqrtf(nb) : 0.f;
                R00 = b0 * ih;  R01 = b1 * ih;
                R10 = -b1 * ih; R11 = b0 * ih;
            } else {
                float ih = (nc2 > 0.f) ? rsqrtf(nc2) : 0.f;
                R00 = c0 * ih;  R01 = c1 * ih;
                R10 = c1 * ih;  R11 = -c0 * ih;
            }
            const float tdx = ctx - (R00 * csx + R01 * csy);
            const float tdy = cty - (R10 * csx + R11 * csy);

            // Applied delta rotation = normalize(R00, R10) (== vec2mat(atan2)).
            const float nn2 = R00 * R00 + R10 * R10;
            const float inh = (nn2 > 0.f) ? rsqrtf(nn2) : 0.f;
            const float cd = R00 * inh, sd = R10 * inh;

            const float nc  = cd * Tc - sd * Ts;     // old T_it still live
            const float ns  = sd * Tc + cd * Ts;
            const float ntx = cd * Tx - sd * Ty + tdx;
            const float nty = sd * Tx + cd * Ty + tdy;

            g_T[b * 4 + 0] = nc;  g_T[b * 4 + 1] = ns;
            g_T[b * 4 + 2] = ntx; g_T[b * 4 + 3] = nty;

            if (it == 4) {
                out[b * 3 + 0] = atan2f(ns, nc);
                out[b * 3 + 1] = ntx;
                out[b * 3 + 2] = nty;
            }
        }
    }
}

// ---------------------------------------------------------------------------
extern "C" void kernel_launch(void* const* d_in, const int* in_sizes, int n_in,
                              void* d_out, int out_size) {
    const float* source = (const float*)d_in[0];
    const float* target = (const float*)d_in[1];
    const float* init   = (const float*)d_in[2];
    float* out = (float*)d_out;

    for (int it = 0; it < 5; it++)
        iter_kernel<<<NBLK, TPB>>>(source, target, init, out, it);
}

// round 12
// speedup vs baseline: 1.3402x; 1.0767x over previous
#include <cuda_runtime.h>
#include <math.h>

#define BB 32
#define NN 2048
#define MM 2048
#define TPB 128                 // 4 warps per block
#define ROWS_PER_BLK 64         // 2 threads per row (half-M each)
#define BPB (NN / ROWS_PER_BLK) // 32 blocks per batch
#define NBLK (BB * BPB)         // 1024 blocks; 7/SM, 28 warps/SM = 7/SMSP exact
#define HALF_P (MM / 4)         // 512 float4-pairs per M-half
#define LOG2E 1.4426950408889634f
#define CSHIFT 64.0f            // global log2-domain shift (cancels in softmax ratio)

// Scratch (no allocations allowed)
__device__ float    g_T[BB * 4];        // per-batch transform: c, s, tx, ty
__device__ float    g_part[NBLK * 8];   // per-block partial sums
__device__ unsigned g_ctr[BB];          // monotonic per-batch arrival counters

__device__ __forceinline__ float ex2(float x) {
    float y;
    asm("ex2.approx.ftz.f32 %0, %1;" : "=f"(y) : "f"(x));
    return y;
}

// ---------------------------------------------------------------------------
// Single kernel type, 5 launches (stream order = cross-iteration sync).
// 4 warps/block, 7 blocks/SM -> exactly 7 warps per SMSP: cuts the SMSP
// work-quantization loss from 2x20.5K to 7x5.125K FFMA-instr critical path.
// Each warp: 16 rows x 2 lanes/row; lanes 0-15 cover M[0,1024), lanes 16-31
// M[1024,2048); halves merged by one shfl_xor(16) per accumulator (bitwise
// identical in both lanes). Epilogue: last-arriving block per batch does the
// Kabsch update (proven R8 pattern, unchanged).
// ---------------------------------------------------------------------------
__global__ __launch_bounds__(TPB, 7)
void iter_kernel(const float* __restrict__ source,
                 const float* __restrict__ target,
                 const float* __restrict__ init,
                 float* __restrict__ out,
                 int it) {
    __shared__ float4 smT[MM / 2];   // 16 KB: (tx0, ty0, tx1, ty1) — raw copy
    __shared__ float2 smC[MM / 2];   //  8 KB: (c0, c1), c = -log2e*|t|^2 - CSHIFT
    __shared__ float  red[4][8];
    __shared__ unsigned s_win;

    const int tid  = threadIdx.x;
    const int wid  = tid >> 5;
    const int lane = tid & 31;
    const int b    = blockIdx.x >> 5;
    const int blk  = blockIdx.x & 31;

    // ---- smem fill: verbatim tile copy + per-pair c coefficients ----
    const float4* tg = (const float4*)(target + (size_t)b * MM * 2);
#pragma unroll
    for (int i = 0; i < MM / 2 / TPB; i++) {   // 8 iterations
        int p = tid + i * TPB;
        float4 q = tg[p];                      // tx0, ty0, tx1, ty1
        smT[p] = q;
        smC[p] = make_float2(fmaf(-LOG2E, q.x * q.x + q.y * q.y, -CSHIFT),
                             fmaf(-LOG2E, q.z * q.z + q.w * q.w, -CSHIFT));
    }

    // ---- transform for this iteration (T_it) ----
    float Tc, Ts, Tx, Ty;
    if (it == 0) {
        float th = init[b * 3 + 0];
        Tc = cosf(th); Ts = sinf(th);
        Tx = init[b * 3 + 1]; Ty = init[b * 3 + 2];
    } else {
        Tc = g_T[b * 4 + 0]; Ts = g_T[b * 4 + 1];
        Tx = g_T[b * 4 + 2]; Ty = g_T[b * 4 + 3];
    }

    // Row for this thread: warp covers 16 rows; lanes l and l+16 share row.
    const int row   = blk * ROWS_PER_BLK + wid * 16 + (lane & 15);
    const int mbase = (lane >> 4) * HALF_P;      // 0 or 512 (float4 index)

    const float2 s2 = ((const float2*)source)[b * NN + row];
    const float stx = Tc * s2.x - Ts * s2.y + Tx;
    const float sty = Ts * s2.x + Tc * s2.y + Ty;
    const float px  = 2.f * LOG2E * stx;
    const float py  = 2.f * LOG2E * sty;

    __syncthreads();

    // ---- mainloop: 512 iters, 2 targets each: 10 FFMA + 2 MUFU + 2 LDS ----
    float s0 = 0.f, s1 = 0.f;
    float ax0 = 0.f, ax1 = 0.f;
    float ay0 = 0.f, ay1 = 0.f;

#pragma unroll 8
    for (int p = 0; p < HALF_P; p++) {
        float4 t = smT[mbase + p];
        float2 c = smC[mbase + p];
        float e0 = ex2(fmaf(px, t.x, fmaf(py, t.y, c.x)));
        float e1 = ex2(fmaf(px, t.z, fmaf(py, t.w, c.y)));
        s0 += e0; ax0 = fmaf(e0, t.x, ax0); ay0 = fmaf(e0, t.y, ay0);
        s1 += e1; ax1 = fmaf(e1, t.z, ax1); ay1 = fmaf(e1, t.w, ay1);
    }

    // Merge the two M-halves of this row (lanes l <-> l^16).
    float sS  = s0 + s1;
    float sAx = ax0 + ax1;
    float sAy = ay0 + ay1;
    sS  += __shfl_xor_sync(0xffffffffu, sS, 16);
    sAx += __shfl_xor_sync(0xffffffffu, sAx, 16);
    sAy += __shfl_xor_sync(0xffffffffu, sAy, 16);

    const float inv = 1.0f / sS;
    const float tcx = sAx * inv;
    const float tcy = sAy * inv;

    // ---- 8-term reduction: each row appears in 2 lanes -> exact x0.5 ----
    float v[8];
    v[0] = stx;       v[1] = sty;
    v[2] = tcx;       v[3] = tcy;
    v[4] = stx * tcx; v[5] = stx * tcy;
    v[6] = sty * tcx; v[7] = sty * tcy;
#pragma unroll
    for (int off = 16; off > 0; off >>= 1)
#pragma unroll
        for (int k = 0; k < 8; k++)
            v[k] += __shfl_down_sync(0xffffffffu, v[k], off);
    if (lane == 0)
#pragma unroll
        for (int k = 0; k < 8; k++) red[wid][k] = v[k] * 0.5f;
    __syncthreads();
    if (tid < 8)
        g_part[(b * BPB + blk) * 8 + tid] =
            (red[0][tid] + red[1][tid]) + (red[2][tid] + red[3][tid]);

    // ---- release partials, elect the per-batch updater (last arrival) ----
    __threadfence();
    __syncthreads();
    if (tid == 0) {
        unsigned a = atomicAdd(&g_ctr[b], 1u) + 1u;   // monotonic across replays
        s_win = ((a & 31u) == 0u) ? 1u : 0u;
    }
    __syncthreads();

    // ---- folded update: winner block's warp 0 composes T_{it+1} ----
    if (s_win && tid < 32) {
        __threadfence();   // acquire: order counter observation before reads
        const float4* pp = (const float4*)&g_part[(b * BPB + tid) * 8];
        float4 qa = __ldcg(pp);         // .cg: bypass possibly-stale L1 line
        float4 qb = __ldcg(pp + 1);
        float w[8] = {qa.x, qa.y, qa.z, qa.w, qb.x, qb.y, qb.z, qb.w};
#pragma unroll
        for (int off = 16; off > 0; off >>= 1)
#pragma unroll
            for (int k = 0; k < 8; k++)
                w[k] += __shfl_down_sync(0xffffffffu, w[k], off);

        if (tid == 0) {
            const float inN = 1.0f / (float)NN;
            const float csx = w[0] * inN, csy = w[1] * inN;
            const float ctx = w[2] * inN, cty = w[3] * inN;
            const float H00 = w[4] - w[0] * w[2] * inN;
            const float H01 = w[5] - w[0] * w[3] * inN;
            const float H10 = w[6] - w[1] * w[2] * inN;
            const float H11 = w[7] - w[1] * w[3] * inN;

            // Polar factor of H^T == V U^T of the SVD incl. reflection case.
            const float b0 = H00 + H11, b1 = H10 - H01;
            const float c0 = H00 - H11, c1 = H10 + H01;
            const float nb  = b0 * b0 + b1 * b1;
            const float nc2 = c0 * c0 + c1 * c1;

            float R00, R01, R10, R11;
            if (nb >= nc2) {
                float ih = (nb > 0.f) ? rsqrtf(nb) : 0.f;
                R00 = b0 * ih;  R01 = b1 * ih;
                R10 = -b1 * ih; R11 = b0 * ih;
            } else {
                float ih = (nc2 > 0.f) ? rsqrtf(nc2) : 0.f;
                R00 = c0 * ih;  R01 = c1 * ih;
                R10 = c1 * ih;  R11 = -c0 * ih;
            }
            const float tdx = ctx - (R00 * csx + R01 * csy);
            const float tdy = cty - (R10 * csx + R11 * csy);

            // Applied delta rotation = normalize(R00, R10) (== vec2mat(atan2)).
            const float nn2 = R00 * R00 + R10 * R10;
            const float inh = (nn2 > 0.f) ? rsqrtf(nn2) : 0.f;
            const float cd = R00 * inh, sd = R10 * inh;

            const float nc  = cd * Tc - sd * Ts;     // old T_it still live
            const float ns  = sd * Tc + cd * Ts;
            const float ntx = cd * Tx - sd * Ty + tdx;
            const float nty = sd * Tx + cd * Ty + tdy;

            g_T[b * 4 + 0] = nc;  g_T[b * 4 + 1] = ns;
            g_T[b * 4 + 2] = ntx; g_T[b * 4 + 3] = nty;

            if (it == 4) {
                out[b * 3 + 0] = atan2f(ns, nc);
                out[b * 3 + 1] = ntx;
                out[b * 3 + 2] = nty;
            }
        }
    }
}

// ---------------------------------------------------------------------------
extern "C" void kernel_launch(void* const* d_in, const int* in_sizes, int n_in,
                              void* d_out, int out_size) {
    const float* source = (const float*)d_in[0];
    const float* target = (const float*)d_in[1];
    const float* init   = (const float*)d_in[2];
    float* out = (float*)d_out;

    for (int it = 0; it < 5; it++)
        iter_kernel<<<NBLK, TPB>>>(source, target, init, out, it);
}